// round 1
// baseline (speedup 1.0000x reference)
#include <cuda_runtime.h>
#include <math.h>

// Problem constants (fixed by the dataset config)
#define MM   129
#define BB   4
#define NPTS 512
#define PG   16                 // points per block in energy kernel
#define NPG  (NPTS / PG)        // 32 point-groups per batch

// Derived math constants
// L = 2*pi, h = L/M, tau = 12/M^2, inv4tau = M^2/48
__device__ __constant__ float c_dummy; // (placeholder, unused)

#define LF       6.2831853071795864769f
#define HF       (6.2831853071795864769f / 129.0f)
#define TAUF     (12.0f / (129.0f * 129.0f))
#define INV4TAU  (129.0f * 129.0f / 48.0f)
// D_c = amp_c * (pi/288) * exp(2*tau*k2) / (k2 + (mu_c*shift_c)^2)
#define DCONST   0.0109083078249645598f   // pi/288

// ---------------- scratch (device globals; no allocation allowed) -----------
__device__ float2 g_A[BB][MM][NPTS];   // 1D DFT along x-dim, centered freq index
__device__ float2 g_B[BB][MM][NPTS];   // 1D DFT along y-dim
__device__ float2 g_G[BB][MM][MM];     // Ghat_b(kx,ky) = sum_p a*b
__device__ float2 g_D[MM * MM];        // (D0, D1) per k

// ---------------- Kernel 1: per-point 1D DFTs --------------------------------
// One block per (b,p). Computes gx[m], gy[m] (periodic gaussians sampled on the
// mesh) then the 129-point DFT at centered frequencies f = i-64 via a shared
// twiddle table indexed by (m*f) mod 129.
__global__ void __launch_bounds__(256) dft_kernel(const float* __restrict__ x) {
    int bp = blockIdx.x;             // 0..2047
    int b  = bp >> 9;
    int p  = bp & 511;
    int tid = threadIdx.x;

    __shared__ float  gx[MM];
    __shared__ float  gy[MM];
    __shared__ float2 tw[MM];

    float x0 = x[bp * 2 + 0];
    float x1 = x[bp * 2 + 1];

    // twiddle table: tw[t] = exp(-2*pi*i*t/M)
    for (int t = tid; t < MM; t += blockDim.x) {
        float ang = -LF * (float)t / (float)MM;
        float s, c;
        sincosf(ang, &s, &c);
        tw[t] = make_float2(c, s);
    }
    // sampled periodic gaussians for both dims
    for (int m = tid; m < 2 * MM; m += blockDim.x) {
        int   mm = (m < MM) ? m : (m - MM);
        float xc = (m < MM) ? x0 : x1;
        float d  = xc - (float)mm * HF;
        float dm = d - LF;
        float dp = d + LF;
        float g  = expf(-d * d * INV4TAU)
                 + expf(-dm * dm * INV4TAU)
                 + expf(-dp * dp * INV4TAU);
        if (m < MM) gx[mm] = g; else gy[mm] = g;
    }
    __syncthreads();

    // outputs: 258 (129 for a, 129 for b), centered index i, freq f = i-64
    for (int o = tid; o < 2 * MM; o += blockDim.x) {
        int i    = (o < MM) ? o : (o - MM);
        int neff = i + 65;                 // (i-64) mod 129
        if (neff >= MM) neff -= MM;
        const float* gv = (o < MM) ? gx : gy;

        float re = 0.0f, im = 0.0f;
        int t = 0;
        #pragma unroll 4
        for (int m = 0; m < MM; m++) {
            float2 w  = tw[t];
            float  gm = gv[m];
            re = fmaf(gm, w.x, re);
            im = fmaf(gm, w.y, im);
            t += neff;
            if (t >= MM) t -= MM;
        }
        float2 r = make_float2(re, im);
        if (o < MM) g_A[b][i][p] = r;
        else        g_B[b][i][p] = r;
    }
}

// ---------------- Kernel D: per-k channel weights ----------------------------
__global__ void dweights_kernel(const float* __restrict__ shift0,
                                const float* __restrict__ shift1,
                                const float* __restrict__ amp0,
                                const float* __restrict__ amp1) {
    int k = blockIdx.x * blockDim.x + threadIdx.x;
    if (k >= MM * MM) return;
    int i = k / MM;
    int j = k - i * MM;
    float fx = (float)(i - 64);
    float fy = (float)(j - 64);
    float k2 = fx * fx + fy * fy;
    float e  = expf(2.0f * TAUF * k2);
    float s0 = shift0[0];            // mu0 = 1
    float s1 = shift1[0];            // mu1 = 1
    float2 d;
    d.x = amp0[0] * DCONST * e / (k2 + s0 * s0);
    d.y = amp1[0] * DCONST * e / (k2 + s1 * s1);
    g_D[k] = d;
}

// ---------------- Kernel 2: Ghat accumulation (complex outer-product GEMM) ---
// Ghat[b][kx][ky] = sum_p A[b][kx][p] * B[b][ky][p]
__global__ void __launch_bounds__(1024) outer_kernel() {
    int b  = blockIdx.z;
    int ty = threadIdx.y, tx = threadIdx.x;
    int kx = blockIdx.x * 32 + ty;
    int ky = blockIdx.y * 32 + tx;

    __shared__ float2 As[32][33];
    __shared__ float2 Bs[32][33];

    float2 acc = make_float2(0.0f, 0.0f);
    for (int pc = 0; pc < NPTS; pc += 32) {
        int rowA = blockIdx.x * 32 + ty;
        int rowB = blockIdx.y * 32 + ty;
        As[ty][tx] = (rowA < MM) ? g_A[b][rowA][pc + tx] : make_float2(0.f, 0.f);
        Bs[ty][tx] = (rowB < MM) ? g_B[b][rowB][pc + tx] : make_float2(0.f, 0.f);
        __syncthreads();
        #pragma unroll
        for (int q = 0; q < 32; q++) {
            float2 a  = As[ty][q];
            float2 bb = Bs[tx][q];
            acc.x = fmaf(a.x, bb.x, fmaf(-a.y, bb.y, acc.x));
            acc.y = fmaf(a.x, bb.y, fmaf( a.y, bb.x, acc.y));
        }
        __syncthreads();
    }
    if (kx < MM && ky < MM) g_G[b][kx][ky] = acc;
}

// ---------------- Kernel 3: per-point energy reduction -----------------------
// e_c[p] = sum_k D_c(k) * ( Re(conj(ghat_p) * Ghat_b) - |ghat_p|^2 )
__global__ void __launch_bounds__(256) energy_kernel(float* __restrict__ out) {
    int b  = blockIdx.x >> 5;       // / NPG
    int pg = blockIdx.x & 31;
    int tid = threadIdx.x;

    __shared__ float2 sa[PG][MM];
    __shared__ float2 sb[PG][MM];

    // stage a,b for this point-group (p contiguous in global -> coalesced)
    for (int i = tid; i < PG * MM; i += 256) {
        int n  = i >> 4;
        int pl = i & 15;
        sa[pl][n] = g_A[b][n][pg * PG + pl];
        sb[pl][n] = g_B[b][n][pg * PG + pl];
    }
    __syncthreads();

    int pl    = tid & 15;
    int klane = tid >> 4;

    const float2* __restrict__ Gp = &g_G[b][0][0];

    float e0 = 0.0f, e1 = 0.0f;
    int kx = 0, ky = klane;
    for (int k = klane; k < MM * MM; k += 16) {
        float2 G  = Gp[k];
        float2 d  = g_D[k];
        float2 a  = sa[pl][kx];
        float2 bb = sb[pl][ky];
        float gr = a.x * bb.x - a.y * bb.y;
        float gi = a.x * bb.y + a.y * bb.x;
        float r  = fmaf(gr, G.x, gi * G.y) - fmaf(gr, gr, gi * gi);
        e0 = fmaf(d.x, r, e0);
        e1 = fmaf(d.y, r, e1);
        ky += 16;
        if (ky >= MM) { ky -= MM; kx++; }
    }

    __shared__ float2 red[256];
    red[tid] = make_float2(e0, e1);
    __syncthreads();
    if (tid < PG) {
        float2 s = make_float2(0.0f, 0.0f);
        #pragma unroll
        for (int j = 0; j < 16; j++) {
            float2 v = red[j * 16 + tid];
            s.x += v.x; s.y += v.y;
        }
        int p = pg * PG + tid;
        ((float2*)out)[b * NPTS + p] = s;
    }
}

// ---------------- launch -----------------------------------------------------
extern "C" void kernel_launch(void* const* d_in, const int* in_sizes, int n_in,
                              void* d_out, int out_size) {
    const float* x      = (const float*)d_in[0];   // [4,512,2]
    const float* shift0 = (const float*)d_in[1];   // [1]
    const float* shift1 = (const float*)d_in[2];   // [1]
    const float* amp0   = (const float*)d_in[3];   // [1]
    const float* amp1   = (const float*)d_in[4];   // [1]
    float* out = (float*)d_out;                    // [4,512,2]

    dft_kernel<<<BB * NPTS, 256>>>(x);
    dweights_kernel<<<(MM * MM + 255) / 256, 256>>>(shift0, shift1, amp0, amp1);
    outer_kernel<<<dim3(5, 5, BB), dim3(32, 32)>>>();
    energy_kernel<<<BB * NPG, 256>>>(out);
}

// round 3
// speedup vs baseline: 1.9619x; 1.9619x over previous
#include <cuda_runtime.h>
#include <math.h>

// Problem constants (fixed by the dataset config)
#define MM   129
#define BB   4
#define NPTS 512
#define PG   16                 // points per block in energy kernel
#define NPG  (NPTS / PG)        // 32 point-groups per batch
#define KSPLIT 8
#define CHUNK  ((MM * MM + KSPLIT - 1) / KSPLIT)   // 2081
#define KXMAX  20               // max kx rows touched by one chunk (17 actual)

#define LF       6.2831853071795864769f
#define HF       (6.2831853071795864769f / 129.0f)
#define TAUF     (12.0f / (129.0f * 129.0f))
#define INV4TAU  (129.0f * 129.0f / 48.0f)
// D_c = amp_c * (pi/288) * exp(2*tau*k2) / (k2 + (mu_c*shift_c)^2)
#define DCONST   0.0109083078249645598f   // pi/288

// ---------------- scratch (device globals; no allocation allowed) -----------
__device__ float2 g_A[BB][MM][NPTS];   // 1D DFT along x-dim, centered freq index
__device__ float2 g_B[BB][MM][NPTS];   // 1D DFT along y-dim
__device__ float2 g_G[BB][MM * MM];    // Ghat_b(kx,ky) = sum_p a*b
__device__ float2 g_D[MM * MM];        // (D0, D1) per k
__device__ float2 g_part[KSPLIT][BB * NPTS];   // partial energies

// ---------------- Kernel 1: per-point 1D DFTs (hermitian symmetric) ----------
// One block per (b,p). 130 tasks: (dim in {x,y}) x (f = 0..64). Negative
// frequencies are conj-mirrored since the gaussian samples are real.
__global__ void __launch_bounds__(160) dft_kernel(const float* __restrict__ x) {
    int bp  = blockIdx.x;             // 0..2047
    int b   = bp >> 9;
    int p   = bp & 511;
    int tid = threadIdx.x;

    __shared__ float  gx[MM];
    __shared__ float  gy[MM];
    __shared__ float2 tw[MM];

    float x0 = x[bp * 2 + 0];
    float x1 = x[bp * 2 + 1];

    // twiddle table: tw[t] = exp(-2*pi*i*t/M)
    for (int t = tid; t < MM; t += 160) {
        float ang = -LF * (float)t / (float)MM;
        float s, c;
        sincosf(ang, &s, &c);
        tw[t] = make_float2(c, s);
    }
    // sampled periodic gaussians for both dims
    for (int m = tid; m < 2 * MM; m += 160) {
        int   mm = (m < MM) ? m : (m - MM);
        float xc = (m < MM) ? x0 : x1;
        float d  = xc - (float)mm * HF;
        float dm = d - LF;
        float dp = d + LF;
        float g  = expf(-d * d * INV4TAU)
                 + expf(-dm * dm * INV4TAU)
                 + expf(-dp * dp * INV4TAU);
        if (m < MM) gx[mm] = g; else gy[mm] = g;
    }
    __syncthreads();

    if (tid < 130) {
        int isx = (tid < 65);
        int f   = isx ? tid : (tid - 65);
        const float* __restrict__ gv = isx ? gx : gy;

        float re = 0.0f, im = 0.0f;
        int t = 0;
        #pragma unroll 4
        for (int m = 0; m < MM; m++) {
            float2 w  = tw[t];
            float  gm = gv[m];
            re = fmaf(gm, w.x, re);
            im = fmaf(gm, w.y, im);
            t += f;
            if (t >= MM) t -= MM;
        }
        float2* dst = isx ? &g_A[b][0][0] : &g_B[b][0][0];
        dst[(64 + f) * NPTS + p] = make_float2(re, im);
        if (f > 0) dst[(64 - f) * NPTS + p] = make_float2(re, -im);
    }
}

// ---------------- Kernel D: per-k channel weights ----------------------------
__global__ void dweights_kernel(const float* __restrict__ shift0,
                                const float* __restrict__ shift1,
                                const float* __restrict__ amp0,
                                const float* __restrict__ amp1) {
    int k = blockIdx.x * blockDim.x + threadIdx.x;
    if (k >= MM * MM) return;
    int i = k / MM;
    int j = k - i * MM;
    float fx = (float)(i - 64);
    float fy = (float)(j - 64);
    float k2 = fx * fx + fy * fy;
    float e  = expf(2.0f * TAUF * k2);
    float s0 = shift0[0];            // mu0 = 1
    float s1 = shift1[0];            // mu1 = 1
    float2 d;
    d.x = amp0[0] * DCONST * e / (k2 + s0 * s0);
    d.y = amp1[0] * DCONST * e / (k2 + s1 * s1);
    g_D[k] = d;
}

// ---------------- Kernel 2: Ghat accumulation (complex outer-product GEMM) ---
// Ghat[b][kx][ky] = sum_p A[b][kx][p] * B[b][ky][p]
// 256 threads, each computes a 2x2 register tile (rows ty/ty+16, cols tx/tx+16)
__global__ void __launch_bounds__(256) outer_kernel() {
    int b  = blockIdx.z;
    int tid = threadIdx.x;
    int tx = tid & 15, ty = tid >> 4;

    __shared__ float2 As[32][33];
    __shared__ float2 Bs[32][33];

    int rA = blockIdx.x * 32;
    int rB = blockIdx.y * 32;

    float2 acc00 = make_float2(0.f, 0.f), acc01 = make_float2(0.f, 0.f);
    float2 acc10 = make_float2(0.f, 0.f), acc11 = make_float2(0.f, 0.f);

    for (int pc = 0; pc < NPTS; pc += 32) {
        // stage 32x32 tiles; 256 threads -> 4 entries each
        #pragma unroll
        for (int s = 0; s < 4; s++) {
            int idx = s * 256 + tid;          // 0..1023
            int row = idx >> 5;
            int col = idx & 31;
            As[row][col] = (rA + row < MM) ? g_A[b][rA + row][pc + col]
                                           : make_float2(0.f, 0.f);
            Bs[row][col] = (rB + row < MM) ? g_B[b][rB + row][pc + col]
                                           : make_float2(0.f, 0.f);
        }
        __syncthreads();
        #pragma unroll
        for (int q = 0; q < 32; q++) {
            float2 a0 = As[ty][q];
            float2 a1 = As[ty + 16][q];
            float2 b0 = Bs[tx][q];
            float2 b1 = Bs[tx + 16][q];
            acc00.x = fmaf(a0.x, b0.x, fmaf(-a0.y, b0.y, acc00.x));
            acc00.y = fmaf(a0.x, b0.y, fmaf( a0.y, b0.x, acc00.y));
            acc01.x = fmaf(a0.x, b1.x, fmaf(-a0.y, b1.y, acc01.x));
            acc01.y = fmaf(a0.x, b1.y, fmaf( a0.y, b1.x, acc01.y));
            acc10.x = fmaf(a1.x, b0.x, fmaf(-a1.y, b0.y, acc10.x));
            acc10.y = fmaf(a1.x, b0.y, fmaf( a1.y, b0.x, acc10.y));
            acc11.x = fmaf(a1.x, b1.x, fmaf(-a1.y, b1.y, acc11.x));
            acc11.y = fmaf(a1.x, b1.y, fmaf( a1.y, b1.x, acc11.y));
        }
        __syncthreads();
    }
    int kx0 = rA + ty, kx1 = rA + ty + 16;
    int ky0 = rB + tx, ky1 = rB + tx + 16;
    if (kx0 < MM && ky0 < MM) g_G[b][kx0 * MM + ky0] = acc00;
    if (kx0 < MM && ky1 < MM) g_G[b][kx0 * MM + ky1] = acc01;
    if (kx1 < MM && ky0 < MM) g_G[b][kx1 * MM + ky0] = acc10;
    if (kx1 < MM && ky1 < MM) g_G[b][kx1 * MM + ky1] = acc11;
}

// ---------------- Kernel 3: per-point energy partials ------------------------
// e_c[p] = sum_k D_c(k) * ( Re(conj(ghat_p) * Ghat_b) - |ghat_p|^2 )
// grid = KSPLIT * BB * NPG; each block handles 16 points x one k-chunk.
__global__ void __launch_bounds__(256) energy_kernel() {
    int bx  = blockIdx.x;
    int kc  = bx >> 7;               // / (BB*NPG)
    int rem = bx & 127;
    int b   = rem >> 5;
    int pg  = rem & 31;
    int tid = threadIdx.x;

    __shared__ float2 sb[MM * PG];      // [ky][pl]
    __shared__ float2 sa[KXMAX * PG];   // [kx-kx0][pl]
    __shared__ float2 red[256];

    int ks  = kc * CHUNK;
    int ke  = ks + CHUNK; if (ke > MM * MM) ke = MM * MM;
    int kx0 = ks / MM;
    int kx1 = (ke - 1) / MM;
    int nkx = kx1 - kx0 + 1;

    // stage b-spectra ([ky][pl], pl fastest -> coalesced loads)
    for (int i = tid; i < MM * PG; i += 256) {
        int n = i >> 4, pl = i & 15;
        sb[i] = g_B[b][n][pg * PG + pl];
    }
    for (int i = tid; i < nkx * PG; i += 256) {
        int n = i >> 4, pl = i & 15;
        sa[i] = g_A[b][kx0 + n][pg * PG + pl];
    }
    __syncthreads();

    int pl    = tid & 15;
    int klane = tid >> 4;

    const float2* __restrict__ Gp = &g_G[b][0];

    float e0 = 0.0f, e1 = 0.0f;
    int k  = ks + klane;
    int kx = k / MM;
    int ky = k - kx * MM;
    for (; k < ke; k += 16) {
        float2 G  = Gp[k];
        float2 d  = g_D[k];
        float2 a  = sa[(kx - kx0) * PG + pl];
        float2 bb = sb[ky * PG + pl];
        float gr = a.x * bb.x - a.y * bb.y;
        float gi = a.x * bb.y + a.y * bb.x;
        float r  = fmaf(gr, G.x, gi * G.y) - fmaf(gr, gr, gi * gi);
        e0 = fmaf(d.x, r, e0);
        e1 = fmaf(d.y, r, e1);
        ky += 16;
        if (ky >= MM) { ky -= MM; kx++; }
    }

    red[tid] = make_float2(e0, e1);
    __syncthreads();
    if (tid < PG) {
        float2 s = make_float2(0.0f, 0.0f);
        #pragma unroll
        for (int j = 0; j < 16; j++) {
            float2 v = red[j * 16 + tid];
            s.x += v.x; s.y += v.y;
        }
        g_part[kc][(b << 9) + pg * PG + tid] = s;
    }
}

// ---------------- Kernel 4: reduce k-split partials --------------------------
__global__ void reduce_kernel(float* __restrict__ out) {
    int i = blockIdx.x * blockDim.x + threadIdx.x;
    if (i >= BB * NPTS) return;
    float2 s = make_float2(0.0f, 0.0f);
    #pragma unroll
    for (int kc = 0; kc < KSPLIT; kc++) {
        float2 v = g_part[kc][i];
        s.x += v.x; s.y += v.y;
    }
    ((float2*)out)[i] = s;
}

// ---------------- launch -----------------------------------------------------
extern "C" void kernel_launch(void* const* d_in, const int* in_sizes, int n_in,
                              void* d_out, int out_size) {
    const float* x      = (const float*)d_in[0];   // [4,512,2]
    const float* shift0 = (const float*)d_in[1];   // [1]
    const float* shift1 = (const float*)d_in[2];   // [1]
    const float* amp0   = (const float*)d_in[3];   // [1]
    const float* amp1   = (const float*)d_in[4];   // [1]
    float* out = (float*)d_out;                    // [4,512,2]

    dft_kernel<<<BB * NPTS, 160>>>(x);
    dweights_kernel<<<(MM * MM + 255) / 256, 256>>>(shift0, shift1, amp0, amp1);
    outer_kernel<<<dim3(5, 5, BB), 256>>>();
    energy_kernel<<<KSPLIT * BB * NPG, 256>>>();
    reduce_kernel<<<(BB * NPTS + 255) / 256, 256>>>(out);
}

// round 6
// speedup vs baseline: 4.3686x; 2.2268x over previous
#include <cuda_runtime.h>
#include <math.h>

// Problem constants (fixed by the dataset config)
#define MM   129
#define BB   4
#define NPTS 512
#define PG   16                 // points per block in energy kernel
#define NPG  (NPTS / PG)        // 32 point-groups per batch
#define KSPLIT 13               // row chunks over 65 upper-half rows (13 x 5)
#define ROWS_PER 5
#define PSPLIT 4                // point-split in outer kernel
#define NROW 65                 // upper-half rows (kx = 64..128)
#define NK   (NROW * MM)        // 8385 upper-half k entries

#define LF       6.2831853071795864769f
#define TAUF     (12.0f / (129.0f * 129.0f))
#define PI2_12   0.82246703342411321824f   // pi^2/12: gaussian exponent in mesh units
// D_c = amp_c * (pi/288) * exp(2*tau*k2) / (k2 + (mu_c*shift_c)^2)
#define DCONST   0.0109083078249645598f    // pi/288

// ---------------- scratch (device globals; no allocation allowed) -----------
__device__ float2 g_A[BB][MM][NPTS];           // x-spectra (rows 64..128 used)
__device__ float2 g_B[BB][MM][NPTS];           // y-spectra (all rows)
__device__ float2 g_Gp[PSPLIT][BB][NK];        // per-point-slice Ghat partials
__device__ float4 g_GD[BB][NK];                // (G.re, G.im, D0', D1')
__device__ float2 g_D[NK];                     // weighted channel weights
__device__ float2 g_tw[MM];                    // exp(-2 pi i t / M)
__device__ float2 g_part[KSPLIT][BB * NPTS];

// ---------------- Kernel 0: setup (twiddles + weighted D) -------------------
// D'(k) folds the half-plane symmetry weight: 2 for k strictly above center,
// 1 at the center, 0 for the unused left half of the center row.
__global__ void setup_kernel(const float* __restrict__ shift0,
                             const float* __restrict__ shift1,
                             const float* __restrict__ amp0,
                             const float* __restrict__ amp1) {
    int t = blockIdx.x * blockDim.x + threadIdx.x;
    if (t < MM) {
        float ang = -LF * (float)t / (float)MM;
        float s, c;
        sincosf(ang, &s, &c);
        g_tw[t] = make_float2(c, s);
    }
    int k = t - MM;                      // 0..NK-1
    if (t >= MM && k < NK) {
        int r  = k / MM;                 // 0..64 (kx = 64 + r)
        int ky = k - r * MM;
        float fx = (float)r;
        float fy = (float)(ky - 64);
        float k2 = fx * fx + fy * fy;
        float w  = (r > 0) ? 2.0f : ((ky > 64) ? 2.0f : ((ky == 64) ? 1.0f : 0.0f));
        float e  = expf(2.0f * TAUF * k2) * DCONST * w;
        float s0 = shift0[0];
        float s1 = shift1[0];
        float2 d;
        d.x = amp0[0] * e / (k2 + s0 * s0);
        d.y = amp1[0] * e / (k2 + s1 * s1);
        g_D[k] = d;
    }
}

// ---------------- Kernel 1: windowed per-point 1D DFTs ----------------------
// Gaussian support is ~6 mesh points (tap |j-7|=7.5 weighs e^-46), so the
// 129-point DFT collapses to a 15-tap sum around m0 = round(x/h); index wrap
// mod 129 is exactly the periodic-image sum since f is integer.
__global__ void __launch_bounds__(160) dft_kernel(const float* __restrict__ x) {
    int bp  = blockIdx.x;             // 0..2047
    int b   = bp >> 9;
    int p   = bp & 511;
    int tid = threadIdx.x;

    __shared__ float2 tw[MM];
    __shared__ float  gw[2][16];      // 15 taps per dim (+pad)

    float x0 = x[bp * 2 + 0];
    float x1 = x[bp * 2 + 1];

    for (int t = tid; t < MM; t += 160) tw[t] = g_tw[t];

    if (tid < 30) {
        int   dim = tid / 15;
        int   j   = tid - dim * 15;          // 0..14 -> offset j-7
        float u   = (dim ? x1 : x0) * ((float)MM / LF);
        float del = u - floorf(u + 0.5f);    // [-0.5, 0.5]
        float z   = del - (float)(j - 7);
        gw[dim][j] = expf(-PI2_12 * z * z);
    }
    __syncthreads();

    if (tid < 130) {
        int dim = (tid >= 65);
        int f   = dim ? (tid - 65) : tid;    // frequency 0..64
        float u = (dim ? x1 : x0) * ((float)MM / LF);
        int m0  = (int)floorf(u + 0.5f);
        int ms  = (m0 - 7) % MM; if (ms < 0) ms += MM;
        int t   = (ms * f) % MM;

        float re = 0.0f, im = 0.0f;
        const float* __restrict__ gv = gw[dim];
        #pragma unroll
        for (int j = 0; j < 15; j++) {
            float2 w = tw[t];
            float  g = gv[j];
            re = fmaf(g, w.x, re);
            im = fmaf(g, w.y, im);
            t += f; if (t >= MM) t -= MM;
        }
        if (dim == 0) {
            // A only needed on upper-half rows (kx >= 64)
            g_A[b][64 + f][p] = make_float2(re, im);
        } else {
            g_B[b][64 + f][p] = make_float2(re, im);
            if (f) g_B[b][64 - f][p] = make_float2(re, -im);
        }
    }
}

// ---------------- Kernel 2: Ghat partials (upper half, p-split, no atomics) -
// g_Gp[ps][b][r*MM+ky] = sum_{p in slice ps} A[b][64+r][p] * B[b][ky][p]
__global__ void __launch_bounds__(256) outer_kernel() {
    int bz = blockIdx.z;               // b * PSPLIT + ps
    int b  = bz >> 2;
    int ps = bz & 3;
    int tid = threadIdx.x;
    int tx = tid & 15, ty = tid >> 4;

    __shared__ float2 As[32][33];
    __shared__ float2 Bs[32][33];

    int rA = 64 + blockIdx.x * 32;     // 64, 96, 128
    int rB = blockIdx.y * 32;

    float2 acc00 = make_float2(0.f, 0.f), acc01 = make_float2(0.f, 0.f);
    float2 acc10 = make_float2(0.f, 0.f), acc11 = make_float2(0.f, 0.f);

    int p0 = ps * (NPTS / PSPLIT);
    for (int pc = p0; pc < p0 + NPTS / PSPLIT; pc += 32) {
        #pragma unroll
        for (int s = 0; s < 4; s++) {
            int idx = s * 256 + tid;
            int row = idx >> 5;
            int col = idx & 31;
            As[row][col] = (rA + row < MM) ? g_A[b][rA + row][pc + col]
                                           : make_float2(0.f, 0.f);
            Bs[row][col] = (rB + row < MM) ? g_B[b][rB + row][pc + col]
                                           : make_float2(0.f, 0.f);
        }
        __syncthreads();
        #pragma unroll
        for (int q = 0; q < 32; q++) {
            float2 a0 = As[ty][q];
            float2 a1 = As[ty + 16][q];
            float2 b0 = Bs[tx][q];
            float2 b1 = Bs[tx + 16][q];
            acc00.x = fmaf(a0.x, b0.x, fmaf(-a0.y, b0.y, acc00.x));
            acc00.y = fmaf(a0.x, b0.y, fmaf( a0.y, b0.x, acc00.y));
            acc01.x = fmaf(a0.x, b1.x, fmaf(-a0.y, b1.y, acc01.x));
            acc01.y = fmaf(a0.x, b1.y, fmaf( a0.y, b1.x, acc01.y));
            acc10.x = fmaf(a1.x, b0.x, fmaf(-a1.y, b0.y, acc10.x));
            acc10.y = fmaf(a1.x, b0.y, fmaf( a1.y, b0.x, acc10.y));
            acc11.x = fmaf(a1.x, b1.x, fmaf(-a1.y, b1.y, acc11.x));
            acc11.y = fmaf(a1.x, b1.y, fmaf( a1.y, b1.x, acc11.y));
        }
        __syncthreads();
    }
    int r0  = rA - 64 + ty, r1 = r0 + 16;
    int ky0 = rB + tx,      ky1 = ky0 + 16;
    float2* __restrict__ Gp = &g_Gp[ps][b][0];
    if (r0 < NROW && ky0 < MM) Gp[r0 * MM + ky0] = acc00;
    if (r0 < NROW && ky1 < MM) Gp[r0 * MM + ky1] = acc01;
    if (r1 < NROW && ky0 < MM) Gp[r1 * MM + ky0] = acc10;
    if (r1 < NROW && ky1 < MM) Gp[r1 * MM + ky1] = acc11;
}

// ---------------- Kernel 2b: combine slices + interleave D ------------------
__global__ void combine_kernel() {
    int i = blockIdx.x * blockDim.x + threadIdx.x;
    if (i >= BB * NK) return;
    int b = i / NK;
    int k = i - b * NK;
    float2 s = make_float2(0.0f, 0.0f);
    #pragma unroll
    for (int ps = 0; ps < PSPLIT; ps++) {
        float2 v = g_Gp[ps][b][k];
        s.x += v.x; s.y += v.y;
    }
    float2 d = g_D[k];
    g_GD[b][k] = make_float4(s.x, s.y, d.x, d.y);
}

// ---------------- Kernel 3: per-point energy partials (upper half) ----------
// e_c[p] = sum_k D'_c(k) * ( Re(conj(ghat_p) * Ghat_b) - |ghat_p|^2 )
// grid = KSPLIT * BB * NPG; each block: 16 points x 5 upper-half rows.
__global__ void __launch_bounds__(256) energy_kernel() {
    int bx  = blockIdx.x;
    int kc  = bx >> 7;               // / (BB*NPG)
    int rem = bx & 127;
    int b   = rem >> 5;
    int pg  = rem & 31;
    int tid = threadIdx.x;

    __shared__ float2 sb[MM * PG];        // [ky][pl]
    __shared__ float2 sa[ROWS_PER * PG];  // [row][pl]
    __shared__ float2 red[256];

    int r0 = kc * ROWS_PER;               // upper-half row index (kx = 64 + r0)

    for (int i = tid; i < MM * PG; i += 256) {
        int n = i >> 4, pl = i & 15;
        sb[i] = g_B[b][n][pg * PG + pl];
    }
    if (tid < ROWS_PER * PG) {
        int n = tid >> 4, pl = tid & 15;
        sa[tid] = g_A[b][64 + r0 + n][pg * PG + pl];
    }
    __syncthreads();

    int pl    = tid & 15;
    int klane = tid >> 4;

    float e0 = 0.0f, e1 = 0.0f;
    #pragma unroll
    for (int rr = 0; rr < ROWS_PER; rr++) {
        float2 a = sa[rr * PG + pl];
        const float4* __restrict__ gd = &g_GD[b][(r0 + rr) * MM];
        int ky = klane;
        #pragma unroll
        for (int t = 0; t < 8; t++, ky += 16) {
            float4 GD = gd[ky];
            float2 bb = sb[ky * PG + pl];
            float gr = a.x * bb.x - a.y * bb.y;
            float gi = a.x * bb.y + a.y * bb.x;
            float r  = fmaf(gr, GD.x, gi * GD.y) - fmaf(gr, gr, gi * gi);
            e0 = fmaf(GD.z, r, e0);
            e1 = fmaf(GD.w, r, e1);
        }
        if (klane == 0) {                 // ky = 128 tail column
            float4 GD = gd[128];
            float2 bb = sb[128 * PG + pl];
            float gr = a.x * bb.x - a.y * bb.y;
            float gi = a.x * bb.y + a.y * bb.x;
            float r  = fmaf(gr, GD.x, gi * GD.y) - fmaf(gr, gr, gi * gi);
            e0 = fmaf(GD.z, r, e0);
            e1 = fmaf(GD.w, r, e1);
        }
    }

    red[tid] = make_float2(e0, e1);
    __syncthreads();
    if (tid < PG) {
        float2 s = make_float2(0.0f, 0.0f);
        #pragma unroll
        for (int j = 0; j < 16; j++) {
            float2 v = red[j * 16 + tid];
            s.x += v.x; s.y += v.y;
        }
        g_part[kc][(b << 9) + pg * PG + tid] = s;
    }
}

// ---------------- Kernel 4: reduce k-split partials --------------------------
__global__ void reduce_kernel(float* __restrict__ out) {
    int i = blockIdx.x * blockDim.x + threadIdx.x;
    if (i >= BB * NPTS) return;
    float2 s = make_float2(0.0f, 0.0f);
    #pragma unroll
    for (int kc = 0; kc < KSPLIT; kc++) {
        float2 v = g_part[kc][i];
        s.x += v.x; s.y += v.y;
    }
    ((float2*)out)[i] = s;
}

// ---------------- launch -----------------------------------------------------
extern "C" void kernel_launch(void* const* d_in, const int* in_sizes, int n_in,
                              void* d_out, int out_size) {
    const float* x      = (const float*)d_in[0];   // [4,512,2]
    const float* shift0 = (const float*)d_in[1];   // [1]
    const float* shift1 = (const float*)d_in[2];   // [1]
    const float* amp0   = (const float*)d_in[3];   // [1]
    const float* amp1   = (const float*)d_in[4];   // [1]
    float* out = (float*)d_out;                    // [4,512,2]

    int setup_tasks = MM + NK;                     // 129 + 8385
    setup_kernel<<<(setup_tasks + 255) / 256, 256>>>(shift0, shift1, amp0, amp1);
    dft_kernel<<<BB * NPTS, 160>>>(x);
    outer_kernel<<<dim3(3, 5, BB * PSPLIT), 256>>>();
    combine_kernel<<<(BB * NK + 255) / 256, 256>>>();
    energy_kernel<<<KSPLIT * BB * NPG, 256>>>();
    reduce_kernel<<<(BB * NPTS + 255) / 256, 256>>>(out);
}

// round 7
// speedup vs baseline: 4.5576x; 1.0433x over previous
#include <cuda_runtime.h>
#include <math.h>

// Problem constants (fixed by the dataset config)
#define MM   129
#define BB   4
#define NPTS 512
#define PG   32                 // points per block in energy kernel
#define NPG  (NPTS / PG)        // 16 point-groups per batch
#define KSPLIT 13               // row chunks over 65 upper-half rows (13 x 5)
#define ROWS_PER 5
#define PSPLIT 4                // point-split in outer kernel
#define NROW 65                 // upper-half rows (kx = 64..128)
#define NK   (NROW * MM)        // 8385 upper-half k entries

#define LF       6.2831853071795864769f
#define TAUF     (12.0f / (129.0f * 129.0f))
#define PI2_12   0.82246703342411321824f   // pi^2/12: gaussian exponent in mesh units
// D_c = amp_c * (pi/288) * exp(2*tau*k2) / (k2 + (mu_c*shift_c)^2)
#define DCONST   0.0109083078249645598f    // pi/288

// ---------------- scratch (device globals; no allocation allowed) -----------
__device__ float2 g_A[BB][MM][NPTS];           // x-spectra (rows 64..128 used)
__device__ float2 g_B[BB][MM][NPTS];           // y-spectra (all rows)
__device__ float2 g_Gp[PSPLIT][BB][NK];        // per-point-slice Ghat partials
__device__ float4 g_GD[BB][NK];                // (G.re, G.im, D0', D1')
__device__ float2 g_part[KSPLIT][BB * NPTS];

// ---------------- Kernel 1: windowed per-point 1D DFTs ----------------------
// Gaussian support is ~6 mesh points (tap |j-7|=7.5 weighs e^-46), so the
// 129-point DFT collapses to a 15-tap sum around m0 = round(x/h); index wrap
// mod 129 is exactly the periodic-image sum since f is integer. Twiddles are
// generated per-thread by unit-complex rotation (2 sincosf, 15 rotations).
__global__ void __launch_bounds__(160) dft_kernel(const float* __restrict__ x) {
    int bp  = blockIdx.x;             // 0..2047
    int b   = bp >> 9;
    int p   = bp & 511;
    int tid = threadIdx.x;

    __shared__ float gw[2][16];       // 15 taps per dim (+pad)

    float x0 = x[bp * 2 + 0];
    float x1 = x[bp * 2 + 1];

    if (tid < 30) {
        int   dim = tid / 15;
        int   j   = tid - dim * 15;          // 0..14 -> offset j-7
        float u   = (dim ? x1 : x0) * ((float)MM / LF);
        float del = u - floorf(u + 0.5f);    // [-0.5, 0.5]
        float z   = del - (float)(j - 7);
        gw[dim][j] = expf(-PI2_12 * z * z);
    }
    __syncthreads();

    if (tid < 130) {
        int dim = (tid >= 65);
        int f   = dim ? (tid - 65) : tid;    // frequency 0..64
        float u = (dim ? x1 : x0) * ((float)MM / LF);
        int m0  = (int)floorf(u + 0.5f);
        int ms  = (m0 - 7) % MM; if (ms < 0) ms += MM;
        int t0  = (ms * f) % MM;

        float wr, wi, sr, si;
        sincosf(-LF * (float)t0 / (float)MM, &wi, &wr);   // w  = exp(-2pi i t0/M)
        sincosf(-LF * (float)f  / (float)MM, &si, &sr);   // ws = exp(-2pi i f/M)

        float re = 0.0f, im = 0.0f;
        const float* __restrict__ gv = gw[dim];
        #pragma unroll
        for (int j = 0; j < 15; j++) {
            float g = gv[j];
            re = fmaf(g, wr, re);
            im = fmaf(g, wi, im);
            float nwr = wr * sr - wi * si;
            wi = fmaf(wr, si, wi * sr);
            wr = nwr;
        }
        if (dim == 0) {
            // A only needed on upper-half rows (kx >= 64)
            g_A[b][64 + f][p] = make_float2(re, im);
        } else {
            g_B[b][64 + f][p] = make_float2(re, im);
            if (f) g_B[b][64 - f][p] = make_float2(re, -im);
        }
    }
}

// ---------------- Kernel 2: Ghat partials (upper half, p-split, no atomics) -
// g_Gp[ps][b][r*MM+ky] = sum_{p in slice ps} A[b][64+r][p] * B[b][ky][p]
__global__ void __launch_bounds__(256) outer_kernel() {
    int bz = blockIdx.z;               // b * PSPLIT + ps
    int b  = bz >> 2;
    int ps = bz & 3;
    int tid = threadIdx.x;
    int tx = tid & 15, ty = tid >> 4;

    __shared__ float2 As[32][33];
    __shared__ float2 Bs[32][33];

    int rA = 64 + blockIdx.x * 32;     // 64, 96, 128
    int rB = blockIdx.y * 32;

    float2 acc00 = make_float2(0.f, 0.f), acc01 = make_float2(0.f, 0.f);
    float2 acc10 = make_float2(0.f, 0.f), acc11 = make_float2(0.f, 0.f);

    int p0 = ps * (NPTS / PSPLIT);
    for (int pc = p0; pc < p0 + NPTS / PSPLIT; pc += 32) {
        #pragma unroll
        for (int s = 0; s < 4; s++) {
            int idx = s * 256 + tid;
            int row = idx >> 5;
            int col = idx & 31;
            As[row][col] = (rA + row < MM) ? g_A[b][rA + row][pc + col]
                                           : make_float2(0.f, 0.f);
            Bs[row][col] = (rB + row < MM) ? g_B[b][rB + row][pc + col]
                                           : make_float2(0.f, 0.f);
        }
        __syncthreads();
        #pragma unroll
        for (int q = 0; q < 32; q++) {
            float2 a0 = As[ty][q];
            float2 a1 = As[ty + 16][q];
            float2 b0 = Bs[tx][q];
            float2 b1 = Bs[tx + 16][q];
            acc00.x = fmaf(a0.x, b0.x, fmaf(-a0.y, b0.y, acc00.x));
            acc00.y = fmaf(a0.x, b0.y, fmaf( a0.y, b0.x, acc00.y));
            acc01.x = fmaf(a0.x, b1.x, fmaf(-a0.y, b1.y, acc01.x));
            acc01.y = fmaf(a0.x, b1.y, fmaf( a0.y, b1.x, acc01.y));
            acc10.x = fmaf(a1.x, b0.x, fmaf(-a1.y, b0.y, acc10.x));
            acc10.y = fmaf(a1.x, b0.y, fmaf( a1.y, b0.x, acc10.y));
            acc11.x = fmaf(a1.x, b1.x, fmaf(-a1.y, b1.y, acc11.x));
            acc11.y = fmaf(a1.x, b1.y, fmaf( a1.y, b1.x, acc11.y));
        }
        __syncthreads();
    }
    int r0  = rA - 64 + ty, r1 = r0 + 16;
    int ky0 = rB + tx,      ky1 = ky0 + 16;
    float2* __restrict__ Gp = &g_Gp[ps][b][0];
    if (r0 < NROW && ky0 < MM) Gp[r0 * MM + ky0] = acc00;
    if (r0 < NROW && ky1 < MM) Gp[r0 * MM + ky1] = acc01;
    if (r1 < NROW && ky0 < MM) Gp[r1 * MM + ky0] = acc10;
    if (r1 < NROW && ky1 < MM) Gp[r1 * MM + ky1] = acc11;
}

// ---------------- Kernel 2b: combine slices + inline weighted D -------------
// D'(k) folds the half-plane symmetry weight: 2 for k strictly above center,
// 1 at the center, 0 for the unused left half of the center row.
__global__ void combine_kernel(const float* __restrict__ shift0,
                               const float* __restrict__ shift1,
                               const float* __restrict__ amp0,
                               const float* __restrict__ amp1) {
    int i = blockIdx.x * blockDim.x + threadIdx.x;
    if (i >= BB * NK) return;
    int b = i / NK;
    int k = i - b * NK;
    float2 s = make_float2(0.0f, 0.0f);
    #pragma unroll
    for (int ps = 0; ps < PSPLIT; ps++) {
        float2 v = g_Gp[ps][b][k];
        s.x += v.x; s.y += v.y;
    }
    int r  = k / MM;                 // 0..64 (kx = 64 + r)
    int ky = k - r * MM;
    float fx = (float)r;
    float fy = (float)(ky - 64);
    float k2 = fx * fx + fy * fy;
    float w  = (r > 0) ? 2.0f : ((ky > 64) ? 2.0f : ((ky == 64) ? 1.0f : 0.0f));
    float e  = expf(2.0f * TAUF * k2) * DCONST * w;
    float s0 = shift0[0];
    float s1 = shift1[0];
    float d0 = amp0[0] * e / (k2 + s0 * s0);
    float d1 = amp1[0] * e / (k2 + s1 * s1);
    g_GD[b][k] = make_float4(s.x, s.y, d0, d1);
}

// ---------------- Kernel 3: per-point energy partials (upper half) ----------
// e_c[p] = sum_k D'_c(k) * ( Re(conj(ghat_p) * Ghat_b) - |ghat_p|^2 )
// grid = KSPLIT * BB * NPG; each block: 32 points x 5 upper-half rows.
// pl = lane (conflict-free sb reads), klane = warp (GD broadcast per warp).
__global__ void __launch_bounds__(256) energy_kernel() {
    int bx  = blockIdx.x;
    int kc  = bx >> 6;               // / (BB*NPG) = /64
    int rem = bx & 63;
    int b   = rem >> 4;
    int pg  = rem & 15;
    int tid = threadIdx.x;

    __shared__ float2 sb[MM * PG];        // [ky][pl]
    __shared__ float2 sa[ROWS_PER * PG];  // [row][pl]
    __shared__ float2 red[256];

    int r0 = kc * ROWS_PER;               // upper-half row index (kx = 64 + r0)

    for (int i = tid; i < MM * PG; i += 256) {
        int n = i >> 5, pl = i & 31;
        sb[i] = g_B[b][n][pg * PG + pl];
    }
    if (tid < ROWS_PER * PG) {
        int n = tid >> 5, pl = tid & 31;
        sa[tid] = g_A[b][64 + r0 + n][pg * PG + pl];
    }
    __syncthreads();

    int pl    = tid & 31;                 // lane = point
    int klane = tid >> 5;                 // warp = ky stripe (0..7)

    float e0 = 0.0f, e1 = 0.0f;
    #pragma unroll
    for (int rr = 0; rr < ROWS_PER; rr++) {
        float2 a = sa[rr * PG + pl];
        const float4* __restrict__ gd = &g_GD[b][(r0 + rr) * MM];
        int ky = klane;
        #pragma unroll
        for (int t = 0; t < 16; t++, ky += 8) {
            float4 GD = gd[ky];
            float2 bb = sb[ky * PG + pl];
            float gr = a.x * bb.x - a.y * bb.y;
            float gi = a.x * bb.y + a.y * bb.x;
            float r  = fmaf(gr, GD.x, gi * GD.y) - fmaf(gr, gr, gi * gi);
            e0 = fmaf(GD.z, r, e0);
            e1 = fmaf(GD.w, r, e1);
        }
        if (klane == 0) {                 // ky = 128 tail column
            float4 GD = gd[128];
            float2 bb = sb[128 * PG + pl];
            float gr = a.x * bb.x - a.y * bb.y;
            float gi = a.x * bb.y + a.y * bb.x;
            float r  = fmaf(gr, GD.x, gi * GD.y) - fmaf(gr, gr, gi * gi);
            e0 = fmaf(GD.z, r, e0);
            e1 = fmaf(GD.w, r, e1);
        }
    }

    red[tid] = make_float2(e0, e1);
    __syncthreads();
    if (tid < PG) {
        float2 s = make_float2(0.0f, 0.0f);
        #pragma unroll
        for (int j = 0; j < 8; j++) {
            float2 v = red[j * 32 + tid];
            s.x += v.x; s.y += v.y;
        }
        g_part[kc][(b << 9) + pg * PG + tid] = s;
    }
}

// ---------------- Kernel 4: reduce k-split partials --------------------------
__global__ void reduce_kernel(float* __restrict__ out) {
    int i = blockIdx.x * blockDim.x + threadIdx.x;
    if (i >= BB * NPTS) return;
    float2 s = make_float2(0.0f, 0.0f);
    #pragma unroll
    for (int kc = 0; kc < KSPLIT; kc++) {
        float2 v = g_part[kc][i];
        s.x += v.x; s.y += v.y;
    }
    ((float2*)out)[i] = s;
}

// ---------------- launch -----------------------------------------------------
extern "C" void kernel_launch(void* const* d_in, const int* in_sizes, int n_in,
                              void* d_out, int out_size) {
    const float* x      = (const float*)d_in[0];   // [4,512,2]
    const float* shift0 = (const float*)d_in[1];   // [1]
    const float* shift1 = (const float*)d_in[2];   // [1]
    const float* amp0   = (const float*)d_in[3];   // [1]
    const float* amp1   = (const float*)d_in[4];   // [1]
    float* out = (float*)d_out;                    // [4,512,2]

    dft_kernel<<<BB * NPTS, 160>>>(x);
    outer_kernel<<<dim3(3, 5, BB * PSPLIT), 256>>>();
    combine_kernel<<<(BB * NK + 127) / 128, 128>>>(shift0, shift1, amp0, amp1);
    energy_kernel<<<KSPLIT * BB * NPG, 256>>>();
    reduce_kernel<<<(BB * NPTS + 255) / 256, 256>>>(out);
}

// round 8
// speedup vs baseline: 4.7741x; 1.0475x over previous
#include <cuda_runtime.h>
#include <math.h>

// Problem constants (fixed by the dataset config)
#define MM   129
#define BB   4
#define NPTS 512
#define PG   32                 // points per block in energy kernel
#define NPG  (NPTS / PG)        // 16 point-groups per batch
#define KSPLIT 13               // row chunks over 65 upper-half rows (13 x 5)
#define ROWS_PER 5
#define PSPLIT 4                // point-split in outer kernel
#define NROW 65                 // upper-half rows (kx = 64..128)
#define NK   (NROW * MM)        // 8385 upper-half k entries

#define LF       6.2831853071795864769f
#define TAUF     (12.0f / (129.0f * 129.0f))
#define PI2_12   0.82246703342411321824f   // pi^2/12: gaussian exponent in mesh units
// D_c = amp_c * (pi/288) * exp(2*tau*k2) / (k2 + (mu_c*shift_c)^2)
#define DCONST   0.0109083078249645598f    // pi/288

// ---------------- scratch (device globals; no allocation allowed) -----------
__device__ float2 g_A[BB][MM][NPTS];           // x-spectra (rows 64..128 used)
__device__ float2 g_B[BB][MM][NPTS];           // y-spectra (all rows)
__device__ float2 g_Gp[PSPLIT][BB][NK];        // per-point-slice Ghat partials
__device__ float4 g_GD[BB][NK];                // (G.re, G.im, D0', D1')
__device__ float2 g_part[KSPLIT][BB * NPTS];

// ---------------- Kernel 1: windowed per-point 1D DFTs ----------------------
// Gaussian support is ~6 mesh points (tap |j-7|=7.5 weighs e^-46), so the
// 129-point DFT collapses to a 15-tap sum around m0 = round(x/h); index wrap
// mod 129 is exactly the periodic-image sum since f is integer. Twiddles are
// generated per-thread by unit-complex rotation (2 sincosf, 15 rotations).
__global__ void __launch_bounds__(160) dft_kernel(const float* __restrict__ x) {
    int bp  = blockIdx.x;             // 0..2047
    int b   = bp >> 9;
    int p   = bp & 511;
    int tid = threadIdx.x;

    __shared__ float gw[2][16];       // 15 taps per dim (+pad)

    float x0 = x[bp * 2 + 0];
    float x1 = x[bp * 2 + 1];

    if (tid < 30) {
        int   dim = tid / 15;
        int   j   = tid - dim * 15;          // 0..14 -> offset j-7
        float u   = (dim ? x1 : x0) * ((float)MM / LF);
        float del = u - floorf(u + 0.5f);    // [-0.5, 0.5]
        float z   = del - (float)(j - 7);
        gw[dim][j] = expf(-PI2_12 * z * z);
    }
    __syncthreads();

    if (tid < 130) {
        int dim = (tid >= 65);
        int f   = dim ? (tid - 65) : tid;    // frequency 0..64
        float u = (dim ? x1 : x0) * ((float)MM / LF);
        int m0  = (int)floorf(u + 0.5f);
        int ms  = (m0 - 7) % MM; if (ms < 0) ms += MM;
        int t0  = (ms * f) % MM;

        float wr, wi, sr, si;
        sincosf(-LF * (float)t0 / (float)MM, &wi, &wr);   // w  = exp(-2pi i t0/M)
        sincosf(-LF * (float)f  / (float)MM, &si, &sr);   // ws = exp(-2pi i f/M)

        float re = 0.0f, im = 0.0f;
        const float* __restrict__ gv = gw[dim];
        #pragma unroll
        for (int j = 0; j < 15; j++) {
            float g = gv[j];
            re = fmaf(g, wr, re);
            im = fmaf(g, wi, im);
            float nwr = wr * sr - wi * si;
            wi = fmaf(wr, si, wi * sr);
            wr = nwr;
        }
        if (dim == 0) {
            // A only needed on upper-half rows (kx >= 64)
            g_A[b][64 + f][p] = make_float2(re, im);
        } else {
            g_B[b][64 + f][p] = make_float2(re, im);
            if (f) g_B[b][64 - f][p] = make_float2(re, -im);
        }
    }
}

// ---------------- Kernel 2: Ghat partials (upper half, p-split, no atomics) -
// g_Gp[ps][b][r*MM+ky] = sum_{p in slice ps} A[b][64+r][p] * B[b][ky][p]
__global__ void __launch_bounds__(256) outer_kernel() {
    int bz = blockIdx.z;               // b * PSPLIT + ps
    int b  = bz >> 2;
    int ps = bz & 3;
    int tid = threadIdx.x;
    int tx = tid & 15, ty = tid >> 4;

    __shared__ float2 As[32][33];
    __shared__ float2 Bs[32][33];

    int rA = 64 + blockIdx.x * 32;     // 64, 96, 128
    int rB = blockIdx.y * 32;

    float2 acc00 = make_float2(0.f, 0.f), acc01 = make_float2(0.f, 0.f);
    float2 acc10 = make_float2(0.f, 0.f), acc11 = make_float2(0.f, 0.f);

    int p0 = ps * (NPTS / PSPLIT);
    for (int pc = p0; pc < p0 + NPTS / PSPLIT; pc += 32) {
        #pragma unroll
        for (int s = 0; s < 4; s++) {
            int idx = s * 256 + tid;
            int row = idx >> 5;
            int col = idx & 31;
            As[row][col] = (rA + row < MM) ? g_A[b][rA + row][pc + col]
                                           : make_float2(0.f, 0.f);
            Bs[row][col] = (rB + row < MM) ? g_B[b][rB + row][pc + col]
                                           : make_float2(0.f, 0.f);
        }
        __syncthreads();
        #pragma unroll
        for (int q = 0; q < 32; q++) {
            float2 a0 = As[ty][q];
            float2 a1 = As[ty + 16][q];
            float2 b0 = Bs[tx][q];
            float2 b1 = Bs[tx + 16][q];
            acc00.x = fmaf(a0.x, b0.x, fmaf(-a0.y, b0.y, acc00.x));
            acc00.y = fmaf(a0.x, b0.y, fmaf( a0.y, b0.x, acc00.y));
            acc01.x = fmaf(a0.x, b1.x, fmaf(-a0.y, b1.y, acc01.x));
            acc01.y = fmaf(a0.x, b1.y, fmaf( a0.y, b1.x, acc01.y));
            acc10.x = fmaf(a1.x, b0.x, fmaf(-a1.y, b0.y, acc10.x));
            acc10.y = fmaf(a1.x, b0.y, fmaf( a1.y, b0.x, acc10.y));
            acc11.x = fmaf(a1.x, b1.x, fmaf(-a1.y, b1.y, acc11.x));
            acc11.y = fmaf(a1.x, b1.y, fmaf( a1.y, b1.x, acc11.y));
        }
        __syncthreads();
    }
    int r0  = rA - 64 + ty, r1 = r0 + 16;
    int ky0 = rB + tx,      ky1 = ky0 + 16;
    float2* __restrict__ Gp = &g_Gp[ps][b][0];
    if (r0 < NROW && ky0 < MM) Gp[r0 * MM + ky0] = acc00;
    if (r0 < NROW && ky1 < MM) Gp[r0 * MM + ky1] = acc01;
    if (r1 < NROW && ky0 < MM) Gp[r1 * MM + ky0] = acc10;
    if (r1 < NROW && ky1 < MM) Gp[r1 * MM + ky1] = acc11;
}

// ---------------- Kernel 2b: combine slices + inline weighted D -------------
// D'(k) folds the half-plane symmetry weight: 2 for k strictly above center,
// 1 at the center, 0 for the unused left half of the center row.
__global__ void combine_kernel(const float* __restrict__ shift0,
                               const float* __restrict__ shift1,
                               const float* __restrict__ amp0,
                               const float* __restrict__ amp1) {
    int i = blockIdx.x * blockDim.x + threadIdx.x;
    if (i >= BB * NK) return;
    int b = i / NK;
    int k = i - b * NK;
    float2 s = make_float2(0.0f, 0.0f);
    #pragma unroll
    for (int ps = 0; ps < PSPLIT; ps++) {
        float2 v = g_Gp[ps][b][k];
        s.x += v.x; s.y += v.y;
    }
    int r  = k / MM;                 // 0..64 (kx = 64 + r)
    int ky = k - r * MM;
    float fx = (float)r;
    float fy = (float)(ky - 64);
    float k2 = fx * fx + fy * fy;
    float w  = (r > 0) ? 2.0f : ((ky > 64) ? 2.0f : ((ky == 64) ? 1.0f : 0.0f));
    float e  = expf(2.0f * TAUF * k2) * DCONST * w;
    float s0 = shift0[0];
    float s1 = shift1[0];
    float d0 = amp0[0] * e / (k2 + s0 * s0);
    float d1 = amp1[0] * e / (k2 + s1 * s1);
    g_GD[b][k] = make_float4(s.x, s.y, d0, d1);
}

// ---------------- Kernel 3: per-point energy partials (upper half) ----------
// e_c[p] = sum_k D'_c(k) * ( Re(conj(ghat_p) * Ghat_b) - |ghat_p|^2 )
// grid = KSPLIT * BB * NPG; each block: 32 points x 5 upper-half rows.
// GD chunk is staged in shared up front (coalesced, read once per block), so
// the inner loop is pure LDS + FMA: LDS.128 broadcast (GD) + LDS.64 (sb).
__global__ void __launch_bounds__(256) energy_kernel() {
    int bx  = blockIdx.x;
    int kc  = bx >> 6;               // / (BB*NPG) = /64
    int rem = bx & 63;
    int b   = rem >> 4;
    int pg  = rem & 15;
    int tid = threadIdx.x;

    __shared__ float2 sb[MM * PG];          // [ky][pl]    33024 B
    __shared__ float2 sa[ROWS_PER * PG];    // [row][pl]    1280 B
    __shared__ float4 sgd[ROWS_PER * MM];   // [row][ky]   10320 B
    __shared__ float2 red[256];             //              2048 B

    int r0 = kc * ROWS_PER;               // upper-half row index (kx = 64 + r0)

    for (int i = tid; i < MM * PG; i += 256) {
        int n = i >> 5, pl = i & 31;
        sb[i] = g_B[b][n][pg * PG + pl];
    }
    for (int i = tid; i < ROWS_PER * MM; i += 256) {
        sgd[i] = g_GD[b][r0 * MM + i];
    }
    if (tid < ROWS_PER * PG) {
        int n = tid >> 5, pl = tid & 31;
        sa[tid] = g_A[b][64 + r0 + n][pg * PG + pl];
    }
    __syncthreads();

    int pl    = tid & 31;                 // lane = point
    int klane = tid >> 5;                 // warp = ky stripe (0..7)

    float e0 = 0.0f, e1 = 0.0f;
    #pragma unroll
    for (int rr = 0; rr < ROWS_PER; rr++) {
        float2 a = sa[rr * PG + pl];
        const float4* __restrict__ gd = &sgd[rr * MM];
        int ky = klane;
        #pragma unroll 4
        for (int t = 0; t < 16; t++, ky += 8) {
            float4 GD = gd[ky];
            float2 bb = sb[ky * PG + pl];
            float gr = a.x * bb.x - a.y * bb.y;
            float gi = a.x * bb.y + a.y * bb.x;
            float r  = fmaf(gr, GD.x, gi * GD.y) - fmaf(gr, gr, gi * gi);
            e0 = fmaf(GD.z, r, e0);
            e1 = fmaf(GD.w, r, e1);
        }
        if (klane == 0) {                 // ky = 128 tail column
            float4 GD = gd[128];
            float2 bb = sb[128 * PG + pl];
            float gr = a.x * bb.x - a.y * bb.y;
            float gi = a.x * bb.y + a.y * bb.x;
            float r  = fmaf(gr, GD.x, gi * GD.y) - fmaf(gr, gr, gi * gi);
            e0 = fmaf(GD.z, r, e0);
            e1 = fmaf(GD.w, r, e1);
        }
    }

    red[tid] = make_float2(e0, e1);
    __syncthreads();
    if (tid < PG) {
        float2 s = make_float2(0.0f, 0.0f);
        #pragma unroll
        for (int j = 0; j < 8; j++) {
            float2 v = red[j * 32 + tid];
            s.x += v.x; s.y += v.y;
        }
        g_part[kc][(b << 9) + pg * PG + tid] = s;
    }
}

// ---------------- Kernel 4: reduce k-split partials --------------------------
__global__ void reduce_kernel(float* __restrict__ out) {
    int i = blockIdx.x * blockDim.x + threadIdx.x;
    if (i >= BB * NPTS) return;
    float2 s = make_float2(0.0f, 0.0f);
    #pragma unroll
    for (int kc = 0; kc < KSPLIT; kc++) {
        float2 v = g_part[kc][i];
        s.x += v.x; s.y += v.y;
    }
    ((float2*)out)[i] = s;
}

// ---------------- launch -----------------------------------------------------
extern "C" void kernel_launch(void* const* d_in, const int* in_sizes, int n_in,
                              void* d_out, int out_size) {
    const float* x      = (const float*)d_in[0];   // [4,512,2]
    const float* shift0 = (const float*)d_in[1];   // [1]
    const float* shift1 = (const float*)d_in[2];   // [1]
    const float* amp0   = (const float*)d_in[3];   // [1]
    const float* amp1   = (const float*)d_in[4];   // [1]
    float* out = (float*)d_out;                    // [4,512,2]

    dft_kernel<<<BB * NPTS, 160>>>(x);
    outer_kernel<<<dim3(3, 5, BB * PSPLIT), 256>>>();
    combine_kernel<<<(BB * NK + 127) / 128, 128>>>(shift0, shift1, amp0, amp1);
    energy_kernel<<<KSPLIT * BB * NPG, 256>>>();
    reduce_kernel<<<(BB * NPTS + 255) / 256, 256>>>(out);
}

// round 9
// speedup vs baseline: 5.2754x; 1.1050x over previous
#include <cuda_runtime.h>
#include <math.h>

// Problem constants (fixed by the dataset config)
#define MM   129
#define BB   4
#define NPTS 512
#define PG   32                 // points per block in energy kernel
#define NPG  (NPTS / PG)        // 16 point-groups per batch
#define KSPLIT 9                // row chunks over 65 upper-half rows (7-8 each)
#define MAXROWS 8
#define PSPLIT 4                // point-split in outer kernel
#define NROW 65                 // upper-half rows (kx = 64..128)
#define NK   (NROW * MM)        // 8385 upper-half k entries

#define LF       6.2831853071795864769f
#define TAUF     (12.0f / (129.0f * 129.0f))
#define PI2_12   0.82246703342411321824f   // pi^2/12: gaussian exponent in mesh units
// D_c = amp_c * (pi/288) * exp(2*tau*k2) / (k2 + (mu_c*shift_c)^2)
#define DCONST   0.0109083078249645598f    // pi/288

// energy kernel dynamic shared layout (bytes)
#define SB_BYTES   (MM * PG * 8)           // 33024
#define SGD_BYTES  (MAXROWS * MM * 16)     // 16512
#define SA_BYTES   (MAXROWS * PG * 8)      // 2048
#define RED_BYTES  (256 * 8)               // 2048
#define DYN_BYTES  (SB_BYTES + SGD_BYTES + SA_BYTES + RED_BYTES)   // 53632

// ---------------- scratch (device globals; no allocation allowed) -----------
__device__ float2 g_A[BB][MM][NPTS];           // x-spectra (rows 64..128 used)
__device__ float2 g_B[BB][MM][NPTS];           // y-spectra (all rows)
__device__ float2 g_Gp[PSPLIT][BB][NK];        // per-point-slice Ghat partials
__device__ float2 g_part[KSPLIT][BB * NPTS];

// ---------------- Kernel 1: windowed per-point 1D DFTs ----------------------
// Gaussian support is ~6 mesh points (tap |j-7|=7.5 weighs e^-46), so the
// 129-point DFT collapses to a 15-tap sum around m0 = round(x/h); index wrap
// mod 129 is exactly the periodic-image sum since f is integer. Twiddles are
// generated per-thread by unit-complex rotation (2 sincosf, 15 rotations).
__global__ void __launch_bounds__(160) dft_kernel(const float* __restrict__ x) {
    int bp  = blockIdx.x;             // 0..2047
    int b   = bp >> 9;
    int p   = bp & 511;
    int tid = threadIdx.x;

    __shared__ float gw[2][16];       // 15 taps per dim (+pad)

    float x0 = x[bp * 2 + 0];
    float x1 = x[bp * 2 + 1];

    if (tid < 30) {
        int   dim = tid / 15;
        int   j   = tid - dim * 15;          // 0..14 -> offset j-7
        float u   = (dim ? x1 : x0) * ((float)MM / LF);
        float del = u - floorf(u + 0.5f);    // [-0.5, 0.5]
        float z   = del - (float)(j - 7);
        gw[dim][j] = expf(-PI2_12 * z * z);
    }
    __syncthreads();

    if (tid < 130) {
        int dim = (tid >= 65);
        int f   = dim ? (tid - 65) : tid;    // frequency 0..64
        float u = (dim ? x1 : x0) * ((float)MM / LF);
        int m0  = (int)floorf(u + 0.5f);
        int ms  = (m0 - 7) % MM; if (ms < 0) ms += MM;
        int t0  = (ms * f) % MM;

        float wr, wi, sr, si;
        sincosf(-LF * (float)t0 / (float)MM, &wi, &wr);   // w  = exp(-2pi i t0/M)
        sincosf(-LF * (float)f  / (float)MM, &si, &sr);   // ws = exp(-2pi i f/M)

        float re = 0.0f, im = 0.0f;
        const float* __restrict__ gv = gw[dim];
        #pragma unroll
        for (int j = 0; j < 15; j++) {
            float g = gv[j];
            re = fmaf(g, wr, re);
            im = fmaf(g, wi, im);
            float nwr = wr * sr - wi * si;
            wi = fmaf(wr, si, wi * sr);
            wr = nwr;
        }
        if (dim == 0) {
            // A only needed on upper-half rows (kx >= 64)
            g_A[b][64 + f][p] = make_float2(re, im);
        } else {
            g_B[b][64 + f][p] = make_float2(re, im);
            if (f) g_B[b][64 - f][p] = make_float2(re, -im);
        }
    }
}

// ---------------- Kernel 2: Ghat partials (upper half, p-split, no atomics) -
// g_Gp[ps][b][r*MM+ky] = sum_{p in slice ps} A[b][64+r][p] * B[b][ky][p]
__global__ void __launch_bounds__(256) outer_kernel() {
    int bz = blockIdx.z;               // b * PSPLIT + ps
    int b  = bz >> 2;
    int ps = bz & 3;
    int tid = threadIdx.x;
    int tx = tid & 15, ty = tid >> 4;

    __shared__ float2 As[32][33];
    __shared__ float2 Bs[32][33];

    int rA = 64 + blockIdx.x * 32;     // 64, 96, 128
    int rB = blockIdx.y * 32;

    float2 acc00 = make_float2(0.f, 0.f), acc01 = make_float2(0.f, 0.f);
    float2 acc10 = make_float2(0.f, 0.f), acc11 = make_float2(0.f, 0.f);

    int p0 = ps * (NPTS / PSPLIT);
    for (int pc = p0; pc < p0 + NPTS / PSPLIT; pc += 32) {
        #pragma unroll
        for (int s = 0; s < 4; s++) {
            int idx = s * 256 + tid;
            int row = idx >> 5;
            int col = idx & 31;
            As[row][col] = (rA + row < MM) ? g_A[b][rA + row][pc + col]
                                           : make_float2(0.f, 0.f);
            Bs[row][col] = (rB + row < MM) ? g_B[b][rB + row][pc + col]
                                           : make_float2(0.f, 0.f);
        }
        __syncthreads();
        #pragma unroll
        for (int q = 0; q < 32; q++) {
            float2 a0 = As[ty][q];
            float2 a1 = As[ty + 16][q];
            float2 b0 = Bs[tx][q];
            float2 b1 = Bs[tx + 16][q];
            acc00.x = fmaf(a0.x, b0.x, fmaf(-a0.y, b0.y, acc00.x));
            acc00.y = fmaf(a0.x, b0.y, fmaf( a0.y, b0.x, acc00.y));
            acc01.x = fmaf(a0.x, b1.x, fmaf(-a0.y, b1.y, acc01.x));
            acc01.y = fmaf(a0.x, b1.y, fmaf( a0.y, b1.x, acc01.y));
            acc10.x = fmaf(a1.x, b0.x, fmaf(-a1.y, b0.y, acc10.x));
            acc10.y = fmaf(a1.x, b0.y, fmaf( a1.y, b0.x, acc10.y));
            acc11.x = fmaf(a1.x, b1.x, fmaf(-a1.y, b1.y, acc11.x));
            acc11.y = fmaf(a1.x, b1.y, fmaf( a1.y, b1.x, acc11.y));
        }
        __syncthreads();
    }
    int r0  = rA - 64 + ty, r1 = r0 + 16;
    int ky0 = rB + tx,      ky1 = ky0 + 16;
    float2* __restrict__ Gp = &g_Gp[ps][b][0];
    if (r0 < NROW && ky0 < MM) Gp[r0 * MM + ky0] = acc00;
    if (r0 < NROW && ky1 < MM) Gp[r0 * MM + ky1] = acc01;
    if (r1 < NROW && ky0 < MM) Gp[r1 * MM + ky0] = acc10;
    if (r1 < NROW && ky1 < MM) Gp[r1 * MM + ky1] = acc11;
}

// ---------------- Kernel 3: per-point energy partials (upper half) ----------
// e_c[p] = sum_k D'_c(k) * ( Re(conj(ghat_p) * Ghat_b) - |ghat_p|^2 )
// grid = KSPLIT * BB * NPG = 576 blocks = one wave at 4 CTAs/SM.
// Staging combines the PSPLIT Ghat slices and computes the weighted D inline
// (saves a whole kernel); the inner loop is pure LDS + FMA.
// D'(k) folds the half-plane symmetry weight: 2 strictly above center,
// 1 at the center, 0 for the unused left half of the center row.
__global__ void __launch_bounds__(256) energy_kernel(const float* __restrict__ shift0,
                                                     const float* __restrict__ shift1,
                                                     const float* __restrict__ amp0,
                                                     const float* __restrict__ amp1) {
    extern __shared__ char dynsmem[];
    float2* sb  = (float2*)dynsmem;                               // [ky][pl]
    float4* sgd = (float4*)(dynsmem + SB_BYTES);                  // [row][ky]
    float2* sa  = (float2*)(dynsmem + SB_BYTES + SGD_BYTES);      // [row][pl]
    float2* red = (float2*)(dynsmem + SB_BYTES + SGD_BYTES + SA_BYTES);

    int bx  = blockIdx.x;
    int kc  = bx >> 6;               // / (BB*NPG) = /64
    int rem = bx & 63;
    int b   = rem >> 4;
    int pg  = rem & 15;
    int tid = threadIdx.x;

    int r0    = (kc * NROW) / KSPLIT;        // chunk row range [r0, r1)
    int r1    = ((kc + 1) * NROW) / KSPLIT;
    int nrows = r1 - r0;                     // 7 or 8

    float s0 = shift0[0], s1 = shift1[0];
    float a0c = amp0[0] * DCONST, a1c = amp1[0] * DCONST;

    for (int i = tid; i < MM * PG; i += 256) {
        int n = i >> 5, pl = i & 31;
        sb[i] = g_B[b][n][pg * PG + pl];
    }
    // stage GD: combine PSPLIT slices + inline weighted D
    int kbase = r0 * MM;
    int nk    = nrows * MM;
    for (int i = tid; i < nk; i += 256) {
        int k = kbase + i;
        float2 s = make_float2(0.0f, 0.0f);
        #pragma unroll
        for (int ps = 0; ps < PSPLIT; ps++) {
            float2 v = g_Gp[ps][b][k];
            s.x += v.x; s.y += v.y;
        }
        int r  = k / MM;                 // 0..64 (kx = 64 + r)
        int ky = k - r * MM;
        float fx = (float)r;
        float fy = (float)(ky - 64);
        float k2 = fx * fx + fy * fy;
        float w  = (r > 0) ? 2.0f : ((ky > 64) ? 2.0f : ((ky == 64) ? 1.0f : 0.0f));
        float e  = expf(2.0f * TAUF * k2) * w;
        sgd[i] = make_float4(s.x, s.y,
                             a0c * e / (k2 + s0 * s0),
                             a1c * e / (k2 + s1 * s1));
    }
    if (tid < nrows * PG) {
        int n = tid >> 5, pl = tid & 31;
        sa[tid] = g_A[b][64 + r0 + n][pg * PG + pl];
    }
    __syncthreads();

    int pl    = tid & 31;                 // lane = point
    int klane = tid >> 5;                 // warp = ky stripe (0..7)

    float e0 = 0.0f, e1 = 0.0f;
    for (int rr = 0; rr < nrows; rr++) {
        float2 a = sa[rr * PG + pl];
        const float4* __restrict__ gd = &sgd[rr * MM];
        int ky = klane;
        #pragma unroll 4
        for (int t = 0; t < 16; t++, ky += 8) {
            float4 GD = gd[ky];
            float2 bb = sb[ky * PG + pl];
            float gr = a.x * bb.x - a.y * bb.y;
            float gi = a.x * bb.y + a.y * bb.x;
            float r  = fmaf(gr, GD.x, gi * GD.y) - fmaf(gr, gr, gi * gi);
            e0 = fmaf(GD.z, r, e0);
            e1 = fmaf(GD.w, r, e1);
        }
        if (klane == 0) {                 // ky = 128 tail column
            float4 GD = gd[128];
            float2 bb = sb[128 * PG + pl];
            float gr = a.x * bb.x - a.y * bb.y;
            float gi = a.x * bb.y + a.y * bb.x;
            float r  = fmaf(gr, GD.x, gi * GD.y) - fmaf(gr, gr, gi * gi);
            e0 = fmaf(GD.z, r, e0);
            e1 = fmaf(GD.w, r, e1);
        }
    }

    red[tid] = make_float2(e0, e1);
    __syncthreads();
    if (tid < PG) {
        float2 s = make_float2(0.0f, 0.0f);
        #pragma unroll
        for (int j = 0; j < 8; j++) {
            float2 v = red[j * 32 + tid];
            s.x += v.x; s.y += v.y;
        }
        g_part[kc][(b << 9) + pg * PG + tid] = s;
    }
}

// ---------------- Kernel 4: reduce k-split partials --------------------------
__global__ void reduce_kernel(float* __restrict__ out) {
    int i = blockIdx.x * blockDim.x + threadIdx.x;
    if (i >= BB * NPTS) return;
    float2 s = make_float2(0.0f, 0.0f);
    #pragma unroll
    for (int kc = 0; kc < KSPLIT; kc++) {
        float2 v = g_part[kc][i];
        s.x += v.x; s.y += v.y;
    }
    ((float2*)out)[i] = s;
}

// ---------------- launch -----------------------------------------------------
extern "C" void kernel_launch(void* const* d_in, const int* in_sizes, int n_in,
                              void* d_out, int out_size) {
    const float* x      = (const float*)d_in[0];   // [4,512,2]
    const float* shift0 = (const float*)d_in[1];   // [1]
    const float* shift1 = (const float*)d_in[2];   // [1]
    const float* amp0   = (const float*)d_in[3];   // [1]
    const float* amp1   = (const float*)d_in[4];   // [1]
    float* out = (float*)d_out;                    // [4,512,2]

    cudaFuncSetAttribute(energy_kernel,
                         cudaFuncAttributeMaxDynamicSharedMemorySize, DYN_BYTES);

    dft_kernel<<<BB * NPTS, 160>>>(x);
    outer_kernel<<<dim3(3, 5, BB * PSPLIT), 256>>>();
    energy_kernel<<<KSPLIT * BB * NPG, 256, DYN_BYTES>>>(shift0, shift1, amp0, amp1);
    reduce_kernel<<<(BB * NPTS + 255) / 256, 256>>>(out);
}

// round 11
// speedup vs baseline: 5.5916x; 1.0599x over previous
#include <cuda_runtime.h>
#include <math.h>

// Problem constants (fixed by the dataset config)
#define MM   129
#define BB   4
#define NPTS 512
#define PG   32                 // points per block in energy kernel
#define NPG  (NPTS / PG)        // 16 point-groups per batch
#define KSPLIT 9                // row chunks over 65 upper-half rows (7-8 each)
#define MAXROWS 8
#define PSPLIT 4                // point-split in outer kernel
#define NROW 65                 // upper-half rows (kx = 64..128)
#define NK   (NROW * MM)        // 8385 upper-half k entries

#define LF       6.2831853071795864769f
#define TAUF     (12.0f / (129.0f * 129.0f))
#define PI2_12   0.82246703342411321824f   // pi^2/12: gaussian exponent in mesh units
// D_c = amp_c * (pi/288) * exp(2*tau*k2) / (k2 + (mu_c*shift_c)^2)
#define DCONST   0.0109083078249645598f    // pi/288

// energy kernel dynamic shared layout (bytes)
#define SB_BYTES   (MM * PG * 8)           // 33024
#define SGD_BYTES  (MAXROWS * MM * 16)     // 16512
#define SA_BYTES   (MAXROWS * PG * 8)      // 2048
#define RED_BYTES  (256 * 8)               // 2048
#define DYN_BYTES  (SB_BYTES + SGD_BYTES + SA_BYTES + RED_BYTES)   // 53632

// ---------------- scratch (device globals; no allocation allowed) -----------
__device__ float2 g_A[BB][MM][NPTS];           // x-spectra (rows 64..128 used)
__device__ float2 g_B[BB][MM][NPTS];           // y-spectra (all rows)
__device__ float2 g_Gp[PSPLIT][BB][NK];        // per-point-slice Ghat partials
__device__ float2 g_part[KSPLIT][BB * NPTS];
__device__ unsigned int g_cnt[BB * NPG];       // arrival counters (zero-init; each
                                               // launch leaves them back at zero)

// ---------------- Kernel 1: windowed per-point 1D DFTs ----------------------
// Gaussian support is ~6 mesh points (tap |j-7|=7.5 weighs e^-46), so the
// 129-point DFT collapses to a 15-tap sum around m0 = round(x/h); index wrap
// mod 129 is exactly the periodic-image sum since f is integer. Twiddles are
// generated per-thread by unit-complex rotation (2 sincosf, 15 rotations).
__global__ void __launch_bounds__(160) dft_kernel(const float* __restrict__ x) {
    int bp  = blockIdx.x;             // 0..2047
    int b   = bp >> 9;
    int p   = bp & 511;
    int tid = threadIdx.x;

    __shared__ float gw[2][16];       // 15 taps per dim (+pad)

    float x0 = x[bp * 2 + 0];
    float x1 = x[bp * 2 + 1];

    if (tid < 30) {
        int   dim = tid / 15;
        int   j   = tid - dim * 15;          // 0..14 -> offset j-7
        float u   = (dim ? x1 : x0) * ((float)MM / LF);
        float del = u - floorf(u + 0.5f);    // [-0.5, 0.5]
        float z   = del - (float)(j - 7);
        gw[dim][j] = __expf(-PI2_12 * z * z);
    }
    __syncthreads();

    if (tid < 130) {
        int dim = (tid >= 65);
        int f   = dim ? (tid - 65) : tid;    // frequency 0..64
        float u = (dim ? x1 : x0) * ((float)MM / LF);
        int m0  = (int)floorf(u + 0.5f);
        int ms  = (m0 - 7) % MM; if (ms < 0) ms += MM;
        int t0  = (ms * f) % MM;

        float wr, wi, sr, si;
        __sincosf(-LF * (float)t0 / (float)MM, &wi, &wr);   // w  = exp(-2pi i t0/M)
        __sincosf(-LF * (float)f  / (float)MM, &si, &sr);   // ws = exp(-2pi i f/M)

        float re = 0.0f, im = 0.0f;
        const float* __restrict__ gv = gw[dim];
        #pragma unroll
        for (int j = 0; j < 15; j++) {
            float g = gv[j];
            re = fmaf(g, wr, re);
            im = fmaf(g, wi, im);
            float nwr = wr * sr - wi * si;
            wi = fmaf(wr, si, wi * sr);
            wr = nwr;
        }
        if (dim == 0) {
            // A only needed on upper-half rows (kx >= 64)
            g_A[b][64 + f][p] = make_float2(re, im);
        } else {
            g_B[b][64 + f][p] = make_float2(re, im);
            if (f) g_B[b][64 - f][p] = make_float2(re, -im);
        }
    }
}

// ---------------- Kernel 2: Ghat partials (upper half, p-split, no atomics) -
// g_Gp[ps][b][r*MM+ky] = sum_{p in slice ps} A[b][64+r][p] * B[b][ky][p]
__global__ void __launch_bounds__(256) outer_kernel() {
    int bz = blockIdx.z;               // b * PSPLIT + ps
    int b  = bz >> 2;
    int ps = bz & 3;
    int tid = threadIdx.x;
    int tx = tid & 15, ty = tid >> 4;

    __shared__ float2 As[32][33];
    __shared__ float2 Bs[32][33];

    int rA = 64 + blockIdx.x * 32;     // 64, 96, 128
    int rB = blockIdx.y * 32;

    float2 acc00 = make_float2(0.f, 0.f), acc01 = make_float2(0.f, 0.f);
    float2 acc10 = make_float2(0.f, 0.f), acc11 = make_float2(0.f, 0.f);

    int p0 = ps * (NPTS / PSPLIT);
    for (int pc = p0; pc < p0 + NPTS / PSPLIT; pc += 32) {
        #pragma unroll
        for (int s = 0; s < 4; s++) {
            int idx = s * 256 + tid;
            int row = idx >> 5;
            int col = idx & 31;
            As[row][col] = (rA + row < MM) ? g_A[b][rA + row][pc + col]
                                           : make_float2(0.f, 0.f);
            Bs[row][col] = (rB + row < MM) ? g_B[b][rB + row][pc + col]
                                           : make_float2(0.f, 0.f);
        }
        __syncthreads();
        #pragma unroll
        for (int q = 0; q < 32; q++) {
            float2 a0 = As[ty][q];
            float2 a1 = As[ty + 16][q];
            float2 b0 = Bs[tx][q];
            float2 b1 = Bs[tx + 16][q];
            acc00.x = fmaf(a0.x, b0.x, fmaf(-a0.y, b0.y, acc00.x));
            acc00.y = fmaf(a0.x, b0.y, fmaf( a0.y, b0.x, acc00.y));
            acc01.x = fmaf(a0.x, b1.x, fmaf(-a0.y, b1.y, acc01.x));
            acc01.y = fmaf(a0.x, b1.y, fmaf( a0.y, b1.x, acc01.y));
            acc10.x = fmaf(a1.x, b0.x, fmaf(-a1.y, b0.y, acc10.x));
            acc10.y = fmaf(a1.x, b0.y, fmaf( a1.y, b0.x, acc10.y));
            acc11.x = fmaf(a1.x, b1.x, fmaf(-a1.y, b1.y, acc11.x));
            acc11.y = fmaf(a1.x, b1.y, fmaf( a1.y, b1.x, acc11.y));
        }
        __syncthreads();
    }
    int r0  = rA - 64 + ty, r1 = r0 + 16;
    int ky0 = rB + tx,      ky1 = ky0 + 16;
    float2* __restrict__ Gp = &g_Gp[ps][b][0];
    if (r0 < NROW && ky0 < MM) Gp[r0 * MM + ky0] = acc00;
    if (r0 < NROW && ky1 < MM) Gp[r0 * MM + ky1] = acc01;
    if (r1 < NROW && ky0 < MM) Gp[r1 * MM + ky0] = acc10;
    if (r1 < NROW && ky1 < MM) Gp[r1 * MM + ky1] = acc11;
}

// ---------------- Kernel 3: energy partials + fused final reduction ---------
// e_c[p] = sum_k D'_c(k) * ( Re(conj(ghat_p) * Ghat_b) - |ghat_p|^2 )
// grid = KSPLIT * BB * NPG = 576 blocks = one wave at 4 CTAs/SM.
// The last-arriving block per (b,pg) slot sums the KSPLIT partials in FIXED
// kc order (deterministic) and writes the output; counter resets for replay.
__global__ void __launch_bounds__(256) energy_kernel(const float* __restrict__ shift0,
                                                     const float* __restrict__ shift1,
                                                     const float* __restrict__ amp0,
                                                     const float* __restrict__ amp1,
                                                     float* __restrict__ out) {
    extern __shared__ char dynsmem[];
    float2* sb  = (float2*)dynsmem;                               // [ky][pl]
    float4* sgd = (float4*)(dynsmem + SB_BYTES);                  // [row][ky]
    float2* sa  = (float2*)(dynsmem + SB_BYTES + SGD_BYTES);      // [row][pl]
    float2* red = (float2*)(dynsmem + SB_BYTES + SGD_BYTES + SA_BYTES);

    int bx  = blockIdx.x;
    int kc  = bx >> 6;               // / (BB*NPG) = /64
    int rem = bx & 63;
    int b   = rem >> 4;
    int pg  = rem & 15;
    int tid = threadIdx.x;

    int r0    = (kc * NROW) / KSPLIT;        // chunk row range [r0, r1)
    int r1    = ((kc + 1) * NROW) / KSPLIT;
    int nrows = r1 - r0;                     // 7 or 8

    float s0 = shift0[0], s1 = shift1[0];
    float a0c = amp0[0] * DCONST, a1c = amp1[0] * DCONST;

    for (int i = tid; i < MM * PG; i += 256) {
        int n = i >> 5, pl = i & 31;
        sb[i] = g_B[b][n][pg * PG + pl];
    }
    // stage GD: combine PSPLIT slices + inline weighted D
    // D'(k) folds the half-plane weight: 2 strictly above center, 1 at the
    // center, 0 for the unused left half of the center row.
    int kbase = r0 * MM;
    int nk    = nrows * MM;
    for (int i = tid; i < nk; i += 256) {
        int k = kbase + i;
        float2 s = make_float2(0.0f, 0.0f);
        #pragma unroll
        for (int ps = 0; ps < PSPLIT; ps++) {
            float2 v = g_Gp[ps][b][k];
            s.x += v.x; s.y += v.y;
        }
        int r  = k / MM;                 // 0..64 (kx = 64 + r)
        int ky = k - r * MM;
        float fx = (float)r;
        float fy = (float)(ky - 64);
        float k2 = fx * fx + fy * fy;
        float w  = (r > 0) ? 2.0f : ((ky > 64) ? 2.0f : ((ky == 64) ? 1.0f : 0.0f));
        float e  = __expf(2.0f * TAUF * k2) * w;
        sgd[i] = make_float4(s.x, s.y,
                             __fdividef(a0c * e, k2 + s0 * s0),
                             __fdividef(a1c * e, k2 + s1 * s1));
    }
    if (tid < nrows * PG) {
        int n = tid >> 5, pl = tid & 31;
        sa[tid] = g_A[b][64 + r0 + n][pg * PG + pl];
    }
    __syncthreads();

    int pl    = tid & 31;                 // lane = point
    int klane = tid >> 5;                 // warp = ky stripe (0..7)

    float e0 = 0.0f, e1 = 0.0f;
    for (int rr = 0; rr < nrows; rr++) {
        float2 a = sa[rr * PG + pl];
        const float4* __restrict__ gd = &sgd[rr * MM];
        int ky = klane;
        #pragma unroll 8
        for (int t = 0; t < 16; t++, ky += 8) {
            float4 GD = gd[ky];
            float2 bb = sb[ky * PG + pl];
            float gr = a.x * bb.x - a.y * bb.y;
            float gi = a.x * bb.y + a.y * bb.x;
            float r  = fmaf(gr, GD.x, gi * GD.y) - fmaf(gr, gr, gi * gi);
            e0 = fmaf(GD.z, r, e0);
            e1 = fmaf(GD.w, r, e1);
        }
        if (klane == 0) {                 // ky = 128 tail column
            float4 GD = gd[128];
            float2 bb = sb[128 * PG + pl];
            float gr = a.x * bb.x - a.y * bb.y;
            float gi = a.x * bb.y + a.y * bb.x;
            float r  = fmaf(gr, GD.x, gi * GD.y) - fmaf(gr, gr, gi * gi);
            e0 = fmaf(GD.z, r, e0);
            e1 = fmaf(GD.w, r, e1);
        }
    }

    red[tid] = make_float2(e0, e1);
    __syncthreads();
    if (tid < PG) {
        float2 s = make_float2(0.0f, 0.0f);
        #pragma unroll
        for (int j = 0; j < 8; j++) {
            float2 v = red[j * 32 + tid];
            s.x += v.x; s.y += v.y;
        }
        g_part[kc][(b << 9) + pg * PG + tid] = s;
    }
    __threadfence();
    __syncthreads();

    // ---- last-block fused reduction (deterministic: fixed kc order) ----
    __shared__ unsigned int s_last;
    if (tid == 0)
        s_last = (atomicAdd(&g_cnt[(b << 4) + pg], 1u) == KSPLIT - 1) ? 1u : 0u;
    __syncthreads();
    if (s_last) {
        if (tid < PG) {
            int idx = (b << 9) + pg * PG + tid;
            float2 s = make_float2(0.0f, 0.0f);
            #pragma unroll
            for (int k2c = 0; k2c < KSPLIT; k2c++) {
                float2 v = g_part[k2c][idx];
                s.x += v.x; s.y += v.y;
            }
            ((float2*)out)[idx] = s;
        }
        if (tid == 0) g_cnt[(b << 4) + pg] = 0u;   // reset for next replay
    }
}

// ---------------- launch -----------------------------------------------------
extern "C" void kernel_launch(void* const* d_in, const int* in_sizes, int n_in,
                              void* d_out, int out_size) {
    const float* x      = (const float*)d_in[0];   // [4,512,2]
    const float* shift0 = (const float*)d_in[1];   // [1]
    const float* shift1 = (const float*)d_in[2];   // [1]
    const float* amp0   = (const float*)d_in[3];   // [1]
    const float* amp1   = (const float*)d_in[4];   // [1]
    float* out = (float*)d_out;                    // [4,512,2]

    cudaFuncSetAttribute(energy_kernel,
                         cudaFuncAttributeMaxDynamicSharedMemorySize, DYN_BYTES);

    dft_kernel<<<BB * NPTS, 160>>>(x);
    outer_kernel<<<dim3(3, 5, BB * PSPLIT), 256>>>();
    energy_kernel<<<KSPLIT * BB * NPG, 256, DYN_BYTES>>>(shift0, shift1, amp0, amp1, out);
}